// round 1
// baseline (speedup 1.0000x reference)
#include <cuda_runtime.h>

// diff[K, N, D] = x[None, :, :] - centroid[:, None, :]
// N=65536, K=32, D=64, fp32. Pure store-bandwidth problem:
// 536 MB out, 16 MB in. Each thread owns one float4 of x, writes K outputs.

#define N_PTS 65536
#define K_CENT 32
#define D_DIM 64
#define D4 (D_DIM / 4)            // 16 float4 per row
#define CENT_F4 (K_CENT * D4)     // 512 float4 = 8 KB

__global__ void __launch_bounds__(256, 8)
kmeans_diff_kernel(const float4* __restrict__ x,
                   const float4* __restrict__ cent,
                   float4* __restrict__ out) {
    __shared__ float4 sc[CENT_F4];

    // Stage centroid tile (8 KB) into shared once per block.
    for (int i = threadIdx.x; i < CENT_F4; i += blockDim.x)
        sc[i] = cent[i];
    __syncthreads();

    const unsigned idx = blockIdx.x * blockDim.x + threadIdx.x;  // [0, N*D/4)
    const unsigned d4 = idx & (D4 - 1);

    const float4 xv = x[idx];  // single DRAM read of x per thread

    const size_t plane = (size_t)N_PTS * D4;  // float4 elements per k-plane

#pragma unroll
    for (int k = 0; k < K_CENT; k++) {
        const float4 c = sc[k * D4 + d4];
        float4 r;
        r.x = xv.x - c.x;
        r.y = xv.y - c.y;
        r.z = xv.z - c.z;
        r.w = xv.w - c.w;
        // Streaming store: output is write-once, never re-read -> don't
        // pollute L2 (keeps x resident for other blocks' reads).
        __stcs(out + (size_t)k * plane + idx, r);
    }
}

extern "C" void kernel_launch(void* const* d_in, const int* in_sizes, int n_in,
                              void* d_out, int out_size) {
    const float4* x    = (const float4*)d_in[0];   // [N, D] fp32
    const float4* cent = (const float4*)d_in[1];   // [K, D] fp32
    float4* out        = (float4*)d_out;           // [K, N, D] fp32

    const int total_f4 = N_PTS * D4;               // 1,048,576 threads
    const int threads = 256;
    const int blocks = total_f4 / threads;         // 4096
    kmeans_diff_kernel<<<blocks, threads>>>(x, cent, out);
}